// round 1
// baseline (speedup 1.0000x reference)
#include <cuda_runtime.h>
#include <math.h>

#define B_  8
#define L_  4096
#define D_  1024
#define K_  256
#define N3_ 3072   // 3*D

// Scratch (allocation-free rule: __device__ globals)
__device__ float g_qkv[B_ * L_ * N3_];      // [B,L,3D]  ~403 MB
__device__ float g_kvp[2 * B_ * K_ * D_];   // [p,B,K,D] ~17 MB  (p=0:K_proj, p=1:V_proj)
__device__ float g_sc [B_ * L_ * K_];       // [B,L,K]   ~34 MB

// ---------------------------------------------------------------------------
// Shared 8x8-register-tile FMA core over As[8][128], Bs[8][128]
// ---------------------------------------------------------------------------
__device__ __forceinline__ void fma_tile(const float (*As)[128], const float (*Bs)[128],
                                         float acc[8][8], int tx, int ty)
{
#pragma unroll
    for (int kk = 0; kk < 8; kk++) {
        float4 a0 = *(const float4*)&As[kk][ty * 8];
        float4 a1 = *(const float4*)&As[kk][ty * 8 + 4];
        float4 b0 = *(const float4*)&Bs[kk][tx * 8];
        float4 b1 = *(const float4*)&Bs[kk][tx * 8 + 4];
        float a[8] = {a0.x, a0.y, a0.z, a0.w, a1.x, a1.y, a1.z, a1.w};
        float b[8] = {b0.x, b0.y, b0.z, b0.w, b1.x, b1.y, b1.z, b1.w};
#pragma unroll
        for (int i = 0; i < 8; i++)
#pragma unroll
            for (int j = 0; j < 8; j++)
                acc[i][j] = fmaf(a[i], b[j], acc[i][j]);
    }
}

// ---------------------------------------------------------------------------
// Generic NN SGEMM, C = A*B (+bias), 128x128x8 tile, batched via blockIdx.z
// A: [M,Kred] row-major (lda), B: [Kred,N] row-major (ldb)
// Used for: qkv = x @ W_qkv + b   and   out = P @ V_proj
// ---------------------------------------------------------------------------
__global__ __launch_bounds__(256, 2)
void sgemm_nn(const float* __restrict__ A, int lda, long sA,
              const float* __restrict__ Bm, int ldb, long sB,
              const float* __restrict__ bias,
              float* __restrict__ C, int ldc, long sC,
              int Kred)
{
    __shared__ float As[8][128];
    __shared__ float Bs[8][128];

    const float* Ab = A  + (size_t)blockIdx.z * sA + (size_t)blockIdx.y * 128 * lda;
    const float* Bb = Bm + (size_t)blockIdx.z * sB + blockIdx.x * 128;
    float*       Cb = C  + (size_t)blockIdx.z * sC;

    int t    = threadIdx.x;
    int arow = t >> 1,  aq = (t & 1) * 4;     // A tile: 128 rows x 8 k (transposed store)
    int brow = t >> 5,  bc = (t & 31) * 4;    // B tile: 8 k x 128 cols (direct store)
    int tx   = t & 15,  ty = t >> 4;

    float acc[8][8] = {};

    for (int k0 = 0; k0 < Kred; k0 += 8) {
        float4 av = *(const float4*)(Ab + (size_t)arow * lda + k0 + aq);
        float4 bv = *(const float4*)(Bb + (size_t)(k0 + brow) * ldb + bc);
        __syncthreads();
        As[aq + 0][arow] = av.x;
        As[aq + 1][arow] = av.y;
        As[aq + 2][arow] = av.z;
        As[aq + 3][arow] = av.w;
        *(float4*)&Bs[brow][bc] = bv;
        __syncthreads();
        fma_tile(As, Bs, acc, tx, ty);
    }

    int ccol = blockIdx.x * 128 + tx * 8;
    float4 bi0 = make_float4(0.f, 0.f, 0.f, 0.f), bi1 = bi0;
    if (bias) {
        bi0 = *(const float4*)(bias + ccol);
        bi1 = *(const float4*)(bias + ccol + 4);
    }
#pragma unroll
    for (int i = 0; i < 8; i++) {
        size_t r = (size_t)blockIdx.y * 128 + ty * 8 + i;
        float* cp = Cb + r * ldc + ccol;
        float4 v0 = make_float4(acc[i][0] + bi0.x, acc[i][1] + bi0.y,
                                acc[i][2] + bi0.z, acc[i][3] + bi0.w);
        float4 v1 = make_float4(acc[i][4] + bi1.x, acc[i][5] + bi1.y,
                                acc[i][6] + bi1.z, acc[i][7] + bi1.w);
        *(float4*)cp       = v0;
        *(float4*)(cp + 4) = v1;
    }
}

// ---------------------------------------------------------------------------
// Projection (TN): C[p,b][kc,d] = sum_l H_p[l,kc] * qkv[b,l,(p+1)*D + d]
// grid: (D/128, K/128, 2*B)   (z = b*2 + p)
// ---------------------------------------------------------------------------
__global__ __launch_bounds__(256, 2)
void proj_tn(const float* __restrict__ Hk, const float* __restrict__ Hv,
             const float* __restrict__ qkv, float* __restrict__ kvp)
{
    int p = blockIdx.z & 1;
    int b = blockIdx.z >> 1;
    const float* H  = p ? Hv : Hk;
    const float* Ab = H + blockIdx.y * 128;                                  // [l, kc]
    const float* Bb = qkv + (size_t)b * L_ * N3_ + (p + 1) * D_ + blockIdx.x * 128;

    __shared__ float As[8][128];
    __shared__ float Bs[8][128];

    int t   = threadIdx.x;
    int row = t >> 5, col = (t & 31) * 4;   // 8 l-rows x 128 cols, both direct
    int tx  = t & 15, ty  = t >> 4;

    float acc[8][8] = {};

    for (int l0 = 0; l0 < L_; l0 += 8) {
        float4 av = *(const float4*)(Ab + (size_t)(l0 + row) * K_  + col);
        float4 bv = *(const float4*)(Bb + (size_t)(l0 + row) * N3_ + col);
        __syncthreads();
        *(float4*)&As[row][col] = av;
        *(float4*)&Bs[row][col] = bv;
        __syncthreads();
        fma_tile(As, Bs, acc, tx, ty);
    }

    float* Cb = kvp + ((size_t)(p * B_ + b) * K_ + blockIdx.y * 128 + ty * 8) * D_
                    + blockIdx.x * 128 + tx * 8;
#pragma unroll
    for (int i = 0; i < 8; i++) {
        float* cp = Cb + (size_t)i * D_;
        *(float4*)cp       = make_float4(acc[i][0], acc[i][1], acc[i][2], acc[i][3]);
        *(float4*)(cp + 4) = make_float4(acc[i][4], acc[i][5], acc[i][6], acc[i][7]);
    }
}

// ---------------------------------------------------------------------------
// Scores (NT): S[b][l,kc] = (1/32) * sum_d q[b,l,d] * K_proj[b,kc,d]
// grid: (K/128, L/128, B)
// ---------------------------------------------------------------------------
__global__ __launch_bounds__(256, 2)
void scores_nt(const float* __restrict__ qkv, const float* __restrict__ kvp,
               float* __restrict__ S)
{
    int b = blockIdx.z;
    const float* Ab = qkv + ((size_t)b * L_ + blockIdx.y * 128) * N3_;       // q slice
    const float* Kb = kvp + ((size_t)b * K_ + blockIdx.x * 128) * D_;        // K_proj (p=0)

    __shared__ float As[8][128];
    __shared__ float Bs[8][128];

    int t   = threadIdx.x;
    int row = t >> 1, q4 = (t & 1) * 4;     // both tiles: 128 rows x 8 d, transposed store
    int tx  = t & 15, ty = t >> 4;

    float acc[8][8] = {};

    for (int d0 = 0; d0 < D_; d0 += 8) {
        float4 av = *(const float4*)(Ab + (size_t)row * N3_ + d0 + q4);
        float4 bv = *(const float4*)(Kb + (size_t)row * D_  + d0 + q4);
        __syncthreads();
        As[q4 + 0][row] = av.x;  As[q4 + 1][row] = av.y;
        As[q4 + 2][row] = av.z;  As[q4 + 3][row] = av.w;
        Bs[q4 + 0][row] = bv.x;  Bs[q4 + 1][row] = bv.y;
        Bs[q4 + 2][row] = bv.z;  Bs[q4 + 3][row] = bv.w;
        __syncthreads();
        fma_tile(As, Bs, acc, tx, ty);
    }

    const float scale = 0.03125f;   // 1/sqrt(1024)
    float* Cb = S + ((size_t)b * L_ + blockIdx.y * 128 + ty * 8) * K_
                  + blockIdx.x * 128 + tx * 8;
#pragma unroll
    for (int i = 0; i < 8; i++) {
        float* cp = Cb + (size_t)i * K_;
        *(float4*)cp       = make_float4(acc[i][0] * scale, acc[i][1] * scale,
                                         acc[i][2] * scale, acc[i][3] * scale);
        *(float4*)(cp + 4) = make_float4(acc[i][4] * scale, acc[i][5] * scale,
                                         acc[i][6] * scale, acc[i][7] * scale);
    }
}

// ---------------------------------------------------------------------------
// In-place softmax over K=256, one warp per row, 8 rows per block
// ---------------------------------------------------------------------------
__global__ __launch_bounds__(256)
void softmax256(float* __restrict__ S)
{
    int warp = threadIdx.x >> 5, lane = threadIdx.x & 31;
    size_t row = (size_t)blockIdx.x * 8 + warp;
    float* p = S + row * K_;

    float v[8];
    float m = -INFINITY;
#pragma unroll
    for (int i = 0; i < 8; i++) {
        v[i] = p[lane + i * 32];
        m = fmaxf(m, v[i]);
    }
#pragma unroll
    for (int o = 16; o > 0; o >>= 1) m = fmaxf(m, __shfl_xor_sync(0xffffffffu, m, o));

    float s = 0.f;
#pragma unroll
    for (int i = 0; i < 8; i++) {
        v[i] = __expf(v[i] - m);
        s += v[i];
    }
#pragma unroll
    for (int o = 16; o > 0; o >>= 1) s += __shfl_xor_sync(0xffffffffu, s, o);

    float inv = 1.f / s;
#pragma unroll
    for (int i = 0; i < 8; i++) p[lane + i * 32] = v[i] * inv;
}

// ---------------------------------------------------------------------------
extern "C" void kernel_launch(void* const* d_in, const int* in_sizes, int n_in,
                              void* d_out, int out_size)
{
    const float* x    = (const float*)d_in[0];   // [B,L,D]
    const float* W    = (const float*)d_in[1];   // [D,3D]
    const float* bias = (const float*)d_in[2];   // [3D]
    const float* Hk   = (const float*)d_in[3];   // [L,K]
    const float* Hv   = (const float*)d_in[4];   // [L,K]
    float*       out  = (float*)d_out;           // [B,L,D]

    float *qkv, *kvp, *sc;
    cudaGetSymbolAddress((void**)&qkv, g_qkv);
    cudaGetSymbolAddress((void**)&kvp, g_kvp);
    cudaGetSymbolAddress((void**)&sc,  g_sc);

    // 1) qkv = x @ W_qkv + b_qkv     [32768,3072] x K=1024
    {
        dim3 grid(N3_ / 128, (B_ * L_) / 128, 1);
        sgemm_nn<<<grid, 256>>>(x, D_, 0, W, N3_, 0, bias, qkv, N3_, 0, D_);
    }
    // 2) K_proj / V_proj = H^T @ {k,v}   per (b,p): [256,1024] x K=4096
    {
        dim3 grid(D_ / 128, K_ / 128, 2 * B_);
        proj_tn<<<grid, 256>>>(Hk, Hv, qkv, kvp);
    }
    // 3) scores = q @ K_proj^T / 32      per b: [4096,256] x K=1024
    {
        dim3 grid(K_ / 128, L_ / 128, B_);
        scores_nt<<<grid, 256>>>(qkv, kvp, sc);
    }
    // 4) softmax over K=256
    softmax256<<<(B_ * L_) / 8, 256>>>(sc);

    // 5) out = P @ V_proj               per b: [4096,1024] x K=256
    {
        dim3 grid(D_ / 128, L_ / 128, B_);
        sgemm_nn<<<grid, 256>>>(sc, K_, (long)L_ * K_,
                                kvp + (size_t)B_ * K_ * D_, D_, (long)K_ * D_,
                                nullptr,
                                out, D_, (long)L_ * D_,
                                K_);
    }
}

// round 4
// speedup vs baseline: 1.5428x; 1.5428x over previous
#include <cuda_runtime.h>
#include <cuda_bf16.h>
#include <math.h>
#include <stdint.h>

#define B_  8
#define L_  4096
#define D_  1024
#define K_  256
#define N3_ 3072   // 3*D
#define BL_ (B_*L_)
#define K3_ 3072   // 3*D concat: [hi | lo | hi] x [wh | wh | wl]

// ---------------- scratch (__device__ globals; no allocations allowed) -----
__device__ float g_qkv[(size_t)BL_ * N3_];            // [B,L,3D] fp32
__device__ float g_kvp[2 * B_ * K_ * D_];             // [p,B,K,D]
__device__ float g_sc [(size_t)BL_ * K_];             // [B,L,K]
__device__ __nv_bfloat16 g_xs [(size_t)BL_ * K3_];    // x: [hi | lo | hi]
__device__ __nv_bfloat16 g_wts[(size_t)N3_ * K3_];    // W^T: [wh | wh | wl]

// ---------------- helpers --------------------------------------------------
__device__ __forceinline__ uint32_t smem_u32(const void* p) {
    uint32_t a;
    asm("{ .reg .u64 t; cvta.to.shared.u64 t, %1; cvt.u32.u64 %0, t; }" : "=r"(a) : "l"(p));
    return a;
}
__device__ __forceinline__ void ldsm_x4(uint32_t* r, uint32_t addr) {
    asm volatile("ldmatrix.sync.aligned.m8n8.x4.shared.b16 {%0,%1,%2,%3}, [%4];"
                 : "=r"(r[0]), "=r"(r[1]), "=r"(r[2]), "=r"(r[3]) : "r"(addr));
}
__device__ __forceinline__ void mma16816(float* d, const uint32_t* a, uint32_t b0, uint32_t b1) {
    asm volatile("mma.sync.aligned.m16n8k16.row.col.f32.bf16.bf16.f32 "
                 "{%0,%1,%2,%3}, {%4,%5,%6,%7}, {%8,%9}, {%0,%1,%2,%3};"
                 : "+f"(d[0]), "+f"(d[1]), "+f"(d[2]), "+f"(d[3])
                 : "r"(a[0]), "r"(a[1]), "r"(a[2]), "r"(a[3]), "r"(b0), "r"(b1));
}

// ---------------------------------------------------------------------------
// split x -> [hi(1024) | lo(1024) | hi(1024)]
// ---------------------------------------------------------------------------
__global__ __launch_bounds__(256)
void split_x(const float* __restrict__ x, __nv_bfloat16* __restrict__ xs)
{
    size_t chunk = (size_t)blockIdx.x * 256 + threadIdx.x;   // BL*D/4 chunks
    size_t m  = chunk >> 8;            // D/4 = 256 chunks per row
    int    dq = (int)(chunk & 255) * 4;
    float4 v = *(const float4*)(x + m * D_ + dq);
    __nv_bfloat16 h0 = __float2bfloat16_rn(v.x), h1 = __float2bfloat16_rn(v.y);
    __nv_bfloat16 h2 = __float2bfloat16_rn(v.z), h3 = __float2bfloat16_rn(v.w);
    __nv_bfloat16 l0 = __float2bfloat16_rn(v.x - __bfloat162float(h0));
    __nv_bfloat16 l1 = __float2bfloat16_rn(v.y - __bfloat162float(h1));
    __nv_bfloat16 l2 = __float2bfloat16_rn(v.z - __bfloat162float(h2));
    __nv_bfloat16 l3 = __float2bfloat16_rn(v.w - __bfloat162float(h3));
    __nv_bfloat162 hA(h0, h1), hB(h2, h3), lA(l0, l1), lB(l2, l3);
    __nv_bfloat162* p0 = (__nv_bfloat162*)(xs + m * K3_ + dq);              // hi
    __nv_bfloat162* p1 = (__nv_bfloat162*)(xs + m * K3_ + D_ + dq);        // lo
    __nv_bfloat162* p2 = (__nv_bfloat162*)(xs + m * K3_ + 2 * D_ + dq);    // hi (dup)
    p0[0] = hA; p0[1] = hB;
    p1[0] = lA; p1[1] = lB;
    p2[0] = hA; p2[1] = hB;
}

// ---------------------------------------------------------------------------
// transpose + split W [D, 3D] -> wts [3D, wh | wh | wl]
// ---------------------------------------------------------------------------
__global__ __launch_bounds__(256)
void wsplit(const float* __restrict__ W, __nv_bfloat16* __restrict__ wts)
{
    __shared__ float t[32][33];
    int n = blockIdx.x * 32 + threadIdx.x;
    int d0 = blockIdx.y * 32;
#pragma unroll
    for (int i = threadIdx.y; i < 32; i += 8)
        t[i][threadIdx.x] = W[(size_t)(d0 + i) * N3_ + n];
    __syncthreads();
    int n0 = blockIdx.x * 32;
    int d = d0 + threadIdx.x;
#pragma unroll
    for (int i = threadIdx.y; i < 32; i += 8) {
        float v = t[threadIdx.x][i];
        __nv_bfloat16 h = __float2bfloat16_rn(v);
        __nv_bfloat16 l = __float2bfloat16_rn(v - __bfloat162float(h));
        wts[(size_t)(n0 + i) * K3_ + d]           = h;   // wh
        wts[(size_t)(n0 + i) * K3_ + D_ + d]      = h;   // wh (dup)
        wts[(size_t)(n0 + i) * K3_ + 2 * D_ + d]  = l;   // wl
    }
}

// ---------------------------------------------------------------------------
// GEMM1 via mma.sync bf16: qkv[m,n] = sum_k xs[m,k]*wts[n,k] + bias[n]
// CTA 128x128, warps 2(m)x4(n) -> warp tile 64x32, K-step 32, K total 3072
// ---------------------------------------------------------------------------
#define PAD 40   // smem row length in bf16 (32 data + 8 pad)

__global__ __launch_bounds__(256, 2)
void gemm1_mma(const __nv_bfloat16* __restrict__ xs, const __nv_bfloat16* __restrict__ ws,
               const float* __restrict__ bias, float* __restrict__ qkv)
{
    __shared__ __align__(16) __nv_bfloat16 As[2][128][PAD];
    __shared__ __align__(16) __nv_bfloat16 Bs[2][128][PAD];

    const int tid = threadIdx.x, lane = tid & 31, warp = tid >> 5;
    const int wm = (warp & 1) * 64;       // warp m offset
    const int wn = (warp >> 1) * 32;      // warp n offset
    const int m0 = blockIdx.y * 128, n0 = blockIdx.x * 128;

    const uint32_t aB = smem_u32(&As[0][0][0]);
    const uint32_t bB = smem_u32(&Bs[0][0][0]);
    const int larow = lane & 15;
    const int lacol = (lane >> 4) * 8;

    float acc[4][4][4] = {};

    // preload stage 0
    uint4 pa[2], pb[2];
#pragma unroll
    for (int i = 0; i < 2; i++) {
        int idx = tid + i * 256;
        int row = idx >> 2, c = (idx & 3) * 8;
        pa[i] = *(const uint4*)(xs + (size_t)(m0 + row) * K3_ + c);
        pb[i] = *(const uint4*)(ws + (size_t)(n0 + row) * K3_ + c);
    }
#pragma unroll
    for (int i = 0; i < 2; i++) {
        int idx = tid + i * 256;
        int row = idx >> 2, c = (idx & 3) * 8;
        *(uint4*)(&As[0][row][c]) = pa[i];
        *(uint4*)(&Bs[0][row][c]) = pb[i];
    }
    __syncthreads();

    const int NSTEP = K3_ / 32;   // 96
    for (int s = 0; s < NSTEP; s++) {
        const int buf = s & 1;
        if (s + 1 < NSTEP) {
            int kc = (s + 1) * 32;
#pragma unroll
            for (int i = 0; i < 2; i++) {
                int idx = tid + i * 256;
                int row = idx >> 2, c = (idx & 3) * 8;
                pa[i] = *(const uint4*)(xs + (size_t)(m0 + row) * K3_ + kc + c);
                pb[i] = *(const uint4*)(ws + (size_t)(n0 + row) * K3_ + kc + c);
            }
        }
#pragma unroll
        for (int kk = 0; kk < 32; kk += 16) {
            uint32_t a[4][4], b[2][4];
#pragma unroll
            for (int mi = 0; mi < 4; mi++) {
                uint32_t addr = aB + (uint32_t)(((buf * 128 + wm + mi * 16 + larow) * PAD) + kk + lacol) * 2;
                ldsm_x4(a[mi], addr);
            }
#pragma unroll
            for (int nj = 0; nj < 2; nj++) {
                uint32_t addr = bB + (uint32_t)(((buf * 128 + wn + nj * 16 + larow) * PAD) + kk + lacol) * 2;
                ldsm_x4(b[nj], addr);
            }
#pragma unroll
            for (int mi = 0; mi < 4; mi++)
#pragma unroll
                for (int ni = 0; ni < 4; ni++)
                    mma16816(acc[mi][ni], a[mi], b[ni >> 1][ni & 1], b[ni >> 1][(ni & 1) + 2]);
        }
        if (s + 1 < NSTEP) {
            int ob = (s + 1) & 1;
#pragma unroll
            for (int i = 0; i < 2; i++) {
                int idx = tid + i * 256;
                int row = idx >> 2, c = (idx & 3) * 8;
                *(uint4*)(&As[ob][row][c]) = pa[i];
                *(uint4*)(&Bs[ob][row][c]) = pb[i];
            }
        }
        __syncthreads();
    }

#pragma unroll
    for (int mi = 0; mi < 4; mi++) {
#pragma unroll
        for (int ni = 0; ni < 4; ni++) {
            int n = n0 + wn + ni * 8 + (lane & 3) * 2;
            float2 bv = *(const float2*)(bias + n);
            int m = m0 + wm + mi * 16 + (lane >> 2);
            float* p0 = qkv + (size_t)m * N3_ + n;
            float* p1 = qkv + (size_t)(m + 8) * N3_ + n;
            p0[0] = acc[mi][ni][0] + bv.x;  p0[1] = acc[mi][ni][1] + bv.y;
            p1[0] = acc[mi][ni][2] + bv.x;  p1[1] = acc[mi][ni][3] + bv.y;
        }
    }
}

// ---------------------------------------------------------------------------
// fp32 8x8 register-tile core (remaining GEMMs)
// ---------------------------------------------------------------------------
__device__ __forceinline__ void fma_tile(const float (*As)[128], const float (*Bs)[128],
                                         float acc[8][8], int tx, int ty)
{
#pragma unroll
    for (int kk = 0; kk < 8; kk++) {
        float4 a0 = *(const float4*)&As[kk][ty * 8];
        float4 a1 = *(const float4*)&As[kk][ty * 8 + 4];
        float4 b0 = *(const float4*)&Bs[kk][tx * 8];
        float4 b1 = *(const float4*)&Bs[kk][tx * 8 + 4];
        float a[8] = {a0.x, a0.y, a0.z, a0.w, a1.x, a1.y, a1.z, a1.w};
        float b[8] = {b0.x, b0.y, b0.z, b0.w, b1.x, b1.y, b1.z, b1.w};
#pragma unroll
        for (int i = 0; i < 8; i++)
#pragma unroll
            for (int j = 0; j < 8; j++)
                acc[i][j] = fmaf(a[i], b[j], acc[i][j]);
    }
}

__global__ __launch_bounds__(256, 2)
void sgemm_nn(const float* __restrict__ A, int lda, long sA,
              const float* __restrict__ Bm, int ldb, long sB,
              const float* __restrict__ bias,
              float* __restrict__ C, int ldc, long sC,
              int Kred)
{
    __shared__ float As[8][128];
    __shared__ float Bs[8][128];

    const float* Ab = A  + (size_t)blockIdx.z * sA + (size_t)blockIdx.y * 128 * lda;
    const float* Bb = Bm + (size_t)blockIdx.z * sB + blockIdx.x * 128;
    float*       Cb = C  + (size_t)blockIdx.z * sC;

    int t    = threadIdx.x;
    int arow = t >> 1,  aq = (t & 1) * 4;
    int brow = t >> 5,  bc = (t & 31) * 4;
    int tx   = t & 15,  ty = t >> 4;

    float acc[8][8] = {};

    for (int k0 = 0; k0 < Kred; k0 += 8) {
        float4 av = *(const float4*)(Ab + (size_t)arow * lda + k0 + aq);
        float4 bv = *(const float4*)(Bb + (size_t)(k0 + brow) * ldb + bc);
        __syncthreads();
        As[aq + 0][arow] = av.x;
        As[aq + 1][arow] = av.y;
        As[aq + 2][arow] = av.z;
        As[aq + 3][arow] = av.w;
        *(float4*)&Bs[brow][bc] = bv;
        __syncthreads();
        fma_tile(As, Bs, acc, tx, ty);
    }

    int ccol = blockIdx.x * 128 + tx * 8;
    float4 bi0 = make_float4(0.f, 0.f, 0.f, 0.f), bi1 = bi0;
    if (bias) {
        bi0 = *(const float4*)(bias + ccol);
        bi1 = *(const float4*)(bias + ccol + 4);
    }
#pragma unroll
    for (int i = 0; i < 8; i++) {
        size_t r = (size_t)blockIdx.y * 128 + ty * 8 + i;
        float* cp = Cb + r * ldc + ccol;
        *(float4*)cp       = make_float4(acc[i][0] + bi0.x, acc[i][1] + bi0.y,
                                         acc[i][2] + bi0.z, acc[i][3] + bi0.w);
        *(float4*)(cp + 4) = make_float4(acc[i][4] + bi1.x, acc[i][5] + bi1.y,
                                         acc[i][6] + bi1.z, acc[i][7] + bi1.w);
    }
}

__global__ __launch_bounds__(256, 2)
void proj_tn(const float* __restrict__ Hk, const float* __restrict__ Hv,
             const float* __restrict__ qkv, float* __restrict__ kvp)
{
    int p = blockIdx.z & 1;
    int b = blockIdx.z >> 1;
    const float* H  = p ? Hv : Hk;
    const float* Ab = H + blockIdx.y * 128;
    const float* Bb = qkv + (size_t)b * L_ * N3_ + (p + 1) * D_ + blockIdx.x * 128;

    __shared__ float As[8][128];
    __shared__ float Bs[8][128];

    int t   = threadIdx.x;
    int row = t >> 5, col = (t & 31) * 4;
    int tx  = t & 15, ty  = t >> 4;

    float acc[8][8] = {};

    for (int l0 = 0; l0 < L_; l0 += 8) {
        float4 av = *(const float4*)(Ab + (size_t)(l0 + row) * K_  + col);
        float4 bv = *(const float4*)(Bb + (size_t)(l0 + row) * N3_ + col);
        __syncthreads();
        *(float4*)&As[row][col] = av;
        *(float4*)&Bs[row][col] = bv;
        __syncthreads();
        fma_tile(As, Bs, acc, tx, ty);
    }

    float* Cb = kvp + ((size_t)(p * B_ + b) * K_ + blockIdx.y * 128 + ty * 8) * D_
                    + blockIdx.x * 128 + tx * 8;
#pragma unroll
    for (int i = 0; i < 8; i++) {
        float* cp = Cb + (size_t)i * D_;
        *(float4*)cp       = make_float4(acc[i][0], acc[i][1], acc[i][2], acc[i][3]);
        *(float4*)(cp + 4) = make_float4(acc[i][4], acc[i][5], acc[i][6], acc[i][7]);
    }
}

__global__ __launch_bounds__(256, 2)
void scores_nt(const float* __restrict__ qkv, const float* __restrict__ kvp,
               float* __restrict__ S)
{
    int b = blockIdx.z;
    const float* Ab = qkv + ((size_t)b * L_ + blockIdx.y * 128) * N3_;
    const float* Kb = kvp + ((size_t)b * K_ + blockIdx.x * 128) * D_;

    __shared__ float As[8][128];
    __shared__ float Bs[8][128];

    int t   = threadIdx.x;
    int row = t >> 1, q4 = (t & 1) * 4;
    int tx  = t & 15, ty = t >> 4;

    float acc[8][8] = {};

    for (int d0 = 0; d0 < D_; d0 += 8) {
        float4 av = *(const float4*)(Ab + (size_t)row * N3_ + d0 + q4);
        float4 bv = *(const float4*)(Kb + (size_t)row * D_  + d0 + q4);
        __syncthreads();
        As[q4 + 0][row] = av.x;  As[q4 + 1][row] = av.y;
        As[q4 + 2][row] = av.z;  As[q4 + 3][row] = av.w;
        Bs[q4 + 0][row] = bv.x;  Bs[q4 + 1][row] = bv.y;
        Bs[q4 + 2][row] = bv.z;  Bs[q4 + 3][row] = bv.w;
        __syncthreads();
        fma_tile(As, Bs, acc, tx, ty);
    }

    const float scale = 0.03125f;
    float* Cb = S + ((size_t)b * L_ + blockIdx.y * 128 + ty * 8) * K_
                  + blockIdx.x * 128 + tx * 8;
#pragma unroll
    for (int i = 0; i < 8; i++) {
        float* cp = Cb + (size_t)i * K_;
        *(float4*)cp       = make_float4(acc[i][0] * scale, acc[i][1] * scale,
                                         acc[i][2] * scale, acc[i][3] * scale);
        *(float4*)(cp + 4) = make_float4(acc[i][4] * scale, acc[i][5] * scale,
                                         acc[i][6] * scale, acc[i][7] * scale);
    }
}

__global__ __launch_bounds__(256)
void softmax256(float* __restrict__ S)
{
    int warp = threadIdx.x >> 5, lane = threadIdx.x & 31;
    size_t row = (size_t)blockIdx.x * 8 + warp;
    float* p = S + row * K_;

    float v[8];
    float m = -INFINITY;
#pragma unroll
    for (int i = 0; i < 8; i++) {
        v[i] = p[lane + i * 32];
        m = fmaxf(m, v[i]);
    }
#pragma unroll
    for (int o = 16; o > 0; o >>= 1) m = fmaxf(m, __shfl_xor_sync(0xffffffffu, m, o));

    float s = 0.f;
#pragma unroll
    for (int i = 0; i < 8; i++) {
        v[i] = __expf(v[i] - m);
        s += v[i];
    }
#pragma unroll
    for (int o = 16; o > 0; o >>= 1) s += __shfl_xor_sync(0xffffffffu, s, o);

    float inv = 1.f / s;
#pragma unroll
    for (int i = 0; i < 8; i++) p[lane + i * 32] = v[i] * inv;
}

// ---------------------------------------------------------------------------
extern "C" void kernel_launch(void* const* d_in, const int* in_sizes, int n_in,
                              void* d_out, int out_size)
{
    const float* x    = (const float*)d_in[0];   // [B,L,D]
    const float* W    = (const float*)d_in[1];   // [D,3D]
    const float* bias = (const float*)d_in[2];   // [3D]
    const float* Hk   = (const float*)d_in[3];   // [L,K]
    const float* Hv   = (const float*)d_in[4];   // [L,K]
    float*       out  = (float*)d_out;           // [B,L,D]

    float *qkv, *kvp, *sc;
    __nv_bfloat16 *xs, *wts;
    cudaGetSymbolAddress((void**)&qkv, g_qkv);
    cudaGetSymbolAddress((void**)&kvp, g_kvp);
    cudaGetSymbolAddress((void**)&sc,  g_sc);
    cudaGetSymbolAddress((void**)&xs,  g_xs);
    cudaGetSymbolAddress((void**)&wts, g_wts);

    // 0a) split x -> [hi | lo | hi]
    split_x<<<(size_t)BL_ * D_ / (256 * 4), 256>>>(x, xs);
    // 0b) transpose + split W -> [wh | wh | wl]
    {
        dim3 grid(N3_ / 32, D_ / 32);
        wsplit<<<grid, dim3(32, 8)>>>(W, wts);
    }
    // 1) qkv = x @ W + b  via tensor cores (K=3072: hi*wh + lo*wh + hi*wl)
    {
        dim3 grid(N3_ / 128, BL_ / 128);
        gemm1_mma<<<grid, 256>>>(xs, wts, bias, qkv);
    }
    // 2) K_proj / V_proj = H^T @ {k,v}
    {
        dim3 grid(D_ / 128, K_ / 128, 2 * B_);
        proj_tn<<<grid, 256>>>(Hk, Hv, qkv, kvp);
    }
    // 3) scores = q @ K_proj^T / 32
    {
        dim3 grid(K_ / 128, L_ / 128, B_);
        scores_nt<<<grid, 256>>>(qkv, kvp, sc);
    }
    // 4) softmax over K=256
    softmax256<<<BL_ / 8, 256>>>(sc);
    // 5) out = P @ V_proj
    {
        dim3 grid(D_ / 128, L_ / 128, B_);
        sgemm_nn<<<grid, 256>>>(sc, K_, (long)L_ * K_,
                                kvp + (size_t)B_ * K_ * D_, D_, (long)K_ * D_,
                                nullptr,
                                out, D_, (long)L_ * D_,
                                K_);
    }
}